// round 3
// baseline (speedup 1.0000x reference)
#include <cuda_runtime.h>
#include <cstdint>
#include <cstddef>

#define Tn 1024
#define Bn 512
#define Hn 128
#define In 64
#define G3 384

// 805 MB scratch for precomputed input-side gate projections: xg[b][t][g]
__device__ float g_xg[(size_t)Bn * Tn * G3];

// ---------------------------------------------------------------------------
// Packed f32x2 FMA (Blackwell): d.lo += a.lo*b.lo ; d.hi += a.hi*b.hi
// ---------------------------------------------------------------------------
__device__ __forceinline__ void ffma2(unsigned long long& d,
                                      const unsigned long long a,
                                      const unsigned long long b) {
    asm("fma.rn.f32x2 %0, %1, %2, %0;" : "+l"(d) : "l"(a), "l"(b));
}

__device__ __forceinline__ float hsum2(unsigned long long v) {
    float lo, hi;
    asm("mov.b64 {%0, %1}, %2;" : "=f"(lo), "=f"(hi) : "l"(v));
    return lo + hi;
}

__device__ __forceinline__ float sigf(float x) {
    return __fdividef(1.0f, 1.0f + __expf(-x));
}
__device__ __forceinline__ float tanh_fast(float x) {
    return 1.0f - __fdividef(2.0f, 1.0f + __expf(2.0f * x));
}

// padded h index: insert 4-float gap every 32 (quarters land on distinct banks)
__device__ __forceinline__ int hidx(int k) { return k + ((k >> 5) << 2); }
#define HPAD 144   // per-batch padded h row (max idx 139 -> round 144)

// ---------------------------------------------------------------------------
// Kernel 1: xg[r][g] = x[r][:] . W_ih[g][:] + b_ih[g] + (g<256 ? b_hh[g] : 0)
// (unchanged from round 2)
// ---------------------------------------------------------------------------
#define XG_SMEM_FLOATS (128 * 64 + 96 * 68)
#define XG_SMEM_BYTES  (XG_SMEM_FLOATS * 4)

__global__ void __launch_bounds__(256, 1)
xg_gemm(const float* __restrict__ x,
        const float* __restrict__ Wih,
        const float* __restrict__ bih,
        const float* __restrict__ bhh) {
    extern __shared__ float smg[];
    float* xs = smg;                 // [128][64]
    float* ws = smg + 128 * 64;      // [96][68] padded

    const int tid = threadIdx.x;
    const int r0 = blockIdx.x * 128;
    const int cb = blockIdx.y;       // 0..3 -> 96 gate-cols each

    {
        const float4* xg4 = (const float4*)(x + (size_t)r0 * 64);
        float4* xs4 = (float4*)xs;
        #pragma unroll
        for (int i = tid; i < 128 * 16; i += 256) xs4[i] = xg4[i];
    }
    {
        const float4* wg4 = (const float4*)(Wih + (size_t)cb * 96 * 64);
        #pragma unroll
        for (int i = tid; i < 96 * 16; i += 256) {
            int g = i >> 4, k4 = i & 15;
            *(float4*)(ws + g * 68 + k4 * 4) = wg4[i];
        }
    }
    __syncthreads();

    const int ry = tid >> 4;
    const int cx = tid & 15;

    unsigned long long acc[8][6];
    #pragma unroll
    for (int i = 0; i < 8; i++)
        #pragma unroll
        for (int jj = 0; jj < 6; jj++) acc[i][jj] = 0ULL;

    #pragma unroll
    for (int k4 = 0; k4 < 16; k4++) {
        ulonglong2 wv[6];
        #pragma unroll
        for (int jj = 0; jj < 6; jj++)
            wv[jj] = *(const ulonglong2*)(ws + (cx + 16 * jj) * 68 + k4 * 4);
        #pragma unroll
        for (int i = 0; i < 8; i++) {
            ulonglong2 xv = *(const ulonglong2*)(xs + (ry * 8 + i) * 64 + k4 * 4);
            #pragma unroll
            for (int jj = 0; jj < 6; jj++) {
                ffma2(acc[i][jj], xv.x, wv[jj].x);
                ffma2(acc[i][jj], xv.y, wv[jj].y);
            }
        }
    }

    #pragma unroll
    for (int jj = 0; jj < 6; jj++) {
        const int g = cb * 96 + cx + 16 * jj;
        const float bias = bih[g] + (g < 256 ? bhh[g] : 0.0f);
        #pragma unroll
        for (int i = 0; i < 8; i++) {
            const int r = r0 + ry * 8 + i;
            g_xg[(size_t)r * G3 + g] = hsum2(acc[i][jj]) + bias;
        }
    }
}

// ---------------------------------------------------------------------------
// Kernel 2: GRU recurrence + final FC.
// 128 blocks x 4 batches, 512 threads (16 warps).
// Thread: warp w, lane l -> j = w*8 + (l&7) (hidden unit), q = l>>3 (k-quarter).
// r-gate W row in REGISTERS; z/n gate rows from padded smem [384][132].
// h double-buffered in smem (quarter-padded) -> 1 barrier/step.
// Cross-quarter reduction via warp shuffle reduce-scatter (9 SHFL/thread).
// Lane q computes gates for batch b = q.
// ---------------------------------------------------------------------------
#define GRU_SMEM_FLOATS (384 * 132 + 2 * 4 * HPAD)
#define GRU_SMEM_BYTES  (GRU_SMEM_FLOATS * 4)

__global__ void __launch_bounds__(512, 1)
gru_kernel(const float* __restrict__ Whh,
           const float* __restrict__ bhh,
           const float* __restrict__ Wfc,
           const float* __restrict__ bfc,
           float* __restrict__ out) {
    extern __shared__ float sm[];
    float* Wsh = sm;                       // [384][132]
    float* hs = sm + 384 * 132;            // [2][4][HPAD]

    const int tid = threadIdx.x;
    const int w = tid >> 5;
    const int l = tid & 31;
    const int j = (w << 3) + (l & 7);
    const int q = l >> 3;
    const int b0 = blockIdx.x * 4;

    // Load W_hh into padded smem (float4, coalesced)
    #pragma unroll
    for (int i = tid; i < 384 * 32; i += 512) {
        int g = i >> 5, k4 = i & 31;
        *(float4*)(Wsh + g * 132 + k4 * 4) = ((const float4*)Whh)[i];
    }
    // Zero h buffer 0
    for (int i = tid; i < 4 * HPAD; i += 512) hs[i] = 0.0f;

    const float bn = bhh[256 + j];   // n-gate hidden bias (inside r*(...))
    __syncthreads();

    // r-gate W quarter -> registers (8 x ulonglong2 = 32 regs)
    ulonglong2 wrr[8];
    {
        const ulonglong2* Wr = (const ulonglong2*)(Wsh + j * 132 + q * 32);
        #pragma unroll
        for (int kk = 0; kk < 8; kk++) wrr[kk] = Wr[kk];
    }
    const ulonglong2* Wz = (const ulonglong2*)(Wsh + (j + 128) * 132 + q * 32);
    const ulonglong2* Wn = (const ulonglong2*)(Wsh + (j + 256) * 132 + q * 32);

    const size_t xg_base = ((size_t)(b0 + q) * Tn) * G3 + j;

    for (int t = 0; t < Tn; t++) {
        const float* hrd = hs + (t & 1) * (4 * HPAD);   // read buffer
        float* hwr = hs + ((t & 1) ^ 1) * (4 * HPAD);   // write buffer

        // Prefetch this lane's batch-q input projections (hidden under dots)
        const float* xp = g_xg + xg_base + (size_t)t * G3;
        const float xr = xp[0], xz = xp[128], xn = xp[256];

        unsigned long long acc[3][4];
        #pragma unroll
        for (int g = 0; g < 3; g++)
            #pragma unroll
            for (int b = 0; b < 4; b++) acc[g][b] = 0ULL;

        #pragma unroll
        for (int kk = 0; kk < 8; kk++) {
            const ulonglong2 wr = wrr[kk];
            const ulonglong2 wz = Wz[kk];
            const ulonglong2 wn = Wn[kk];
            #pragma unroll
            for (int b = 0; b < 4; b++) {
                ulonglong2 hv = *(const ulonglong2*)(hrd + b * HPAD + q * 36 + kk * 4);
                ffma2(acc[0][b], wr.x, hv.x); ffma2(acc[0][b], wr.y, hv.y);
                ffma2(acc[1][b], wz.x, hv.x); ffma2(acc[1][b], wz.y, hv.y);
                ffma2(acc[2][b], wn.x, hv.x); ffma2(acc[2][b], wn.y, hv.y);
            }
        }

        // Horizontal sums: 12 floats per thread (3 gates x 4 batches)
        float s[3][4];
        #pragma unroll
        for (int g = 0; g < 3; g++)
            #pragma unroll
            for (int b = 0; b < 4; b++) s[g][b] = hsum2(acc[g][b]);

        // Reduce-scatter over the 4 quarters:
        // round 1 (xor 16 <-> q bit1): keep batches with b_bit1 == q_bit1
        float s2[3][2];
        const int bh = (q & 2);
        #pragma unroll
        for (int g = 0; g < 3; g++)
            #pragma unroll
            for (int i = 0; i < 2; i++) {
                int b = bh + i;
                s2[g][i] = s[g][b] + __shfl_xor_sync(0xFFFFFFFFu, s[g][b ^ 2], 16);
            }
        // round 2 (xor 8 <-> q bit0): keep b == q
        const int i0 = (q & 1);
        float hr_s, hz_s, hn_s;
        hr_s = s2[0][i0] + __shfl_xor_sync(0xFFFFFFFFu, s2[0][i0 ^ 1], 8);
        hz_s = s2[1][i0] + __shfl_xor_sync(0xFFFFFFFFu, s2[1][i0 ^ 1], 8);
        hn_s = s2[2][i0] + __shfl_xor_sync(0xFFFFFFFFu, s2[2][i0 ^ 1], 8);

        // Gates for (j, b=q)
        const float r = sigf(xr + hr_s);
        const float z = sigf(xz + hz_s);
        const float n = tanh_fast(fmaf(r, hn_s + bn, xn));
        const float h = hrd[q * HPAD + hidx(j)];
        hwr[q * HPAD + hidx(j)] = fmaf(z, h - n, n);   // (1-z)*n + z*h

        __syncthreads();
    }

    // Final h lives in buffer 0 (t=1023 wrote buf[(1023+1)&1] = 0).
    // FC: out[b][o] = h_T[b] . W_fc[o] + b_fc[o]
    if (tid < 4 * 51) {
        const int b = tid / 51, o = tid % 51;
        float a = bfc[o];
        const float* wf = Wfc + o * 128;
        const float* hp = hs + b * HPAD;
        #pragma unroll 8
        for (int k = 0; k < 128; k++) a = fmaf(hp[hidx(k)], wf[k], a);
        out[(b0 + b) * 51 + o] = a;
    }
}

// ---------------------------------------------------------------------------
// Launch
// ---------------------------------------------------------------------------
extern "C" void kernel_launch(void* const* d_in, const int* in_sizes, int n_in,
                              void* d_out, int out_size) {
    const float* x    = (const float*)d_in[0];  // [512,1,1024,64]
    const float* Wih  = (const float*)d_in[1];  // [384,64]
    const float* Whh  = (const float*)d_in[2];  // [384,128]
    const float* bih  = (const float*)d_in[3];  // [384]
    const float* bhh  = (const float*)d_in[4];  // [384]
    const float* Wfc  = (const float*)d_in[5];  // [51,128]
    const float* bfc  = (const float*)d_in[6];  // [51]
    float* out = (float*)d_out;                 // [512,51]

    static int attr_done = 0;
    if (!attr_done) {
        cudaFuncSetAttribute(xg_gemm,
                             cudaFuncAttributeMaxDynamicSharedMemorySize,
                             XG_SMEM_BYTES);
        cudaFuncSetAttribute(gru_kernel,
                             cudaFuncAttributeMaxDynamicSharedMemorySize,
                             GRU_SMEM_BYTES);
        attr_done = 1;
    }

    xg_gemm<<<dim3((Bn * Tn) / 128, 4, 1), 256, XG_SMEM_BYTES>>>(x, Wih, bih, bhh);
    gru_kernel<<<128, 512, GRU_SMEM_BYTES>>>(Whh, bhh, Wfc, bfc, out);
}

// round 4
// speedup vs baseline: 1.6358x; 1.6358x over previous
#include <cuda_runtime.h>
#include <cstdint>
#include <cstddef>

#define Tn 1024
#define Bn 512
#define Hn 128
#define In 64
#define G3 384

// 805 MB scratch for precomputed input-side gate projections: xg[b][t][g]
__device__ float g_xg[(size_t)Bn * Tn * G3];

// ---------------------------------------------------------------------------
// Packed f32x2 FMA (Blackwell): d.lo += a.lo*b.lo ; d.hi += a.hi*b.hi
// ---------------------------------------------------------------------------
__device__ __forceinline__ void ffma2(unsigned long long& d,
                                      const unsigned long long a,
                                      const unsigned long long b) {
    asm("fma.rn.f32x2 %0, %1, %2, %0;" : "+l"(d) : "l"(a), "l"(b));
}

__device__ __forceinline__ float hsum2(unsigned long long v) {
    float lo, hi;
    asm("mov.b64 {%0, %1}, %2;" : "=f"(lo), "=f"(hi) : "l"(v));
    return lo + hi;
}

__device__ __forceinline__ float sigf(float x) {
    return __fdividef(1.0f, 1.0f + __expf(-x));
}
__device__ __forceinline__ float tanh_fast(float x) {
    return 1.0f - __fdividef(2.0f, 1.0f + __expf(2.0f * x));
}

// ---------------------------------------------------------------------------
// Kernel 1: xg[r][g] = x[r][:] . W_ih[g][:] + b_ih[g] + (g<256 ? b_hh[g] : 0)
// (unchanged — proven at R2)
// ---------------------------------------------------------------------------
#define XG_SMEM_FLOATS (128 * 64 + 96 * 68)
#define XG_SMEM_BYTES  (XG_SMEM_FLOATS * 4)

__global__ void __launch_bounds__(256, 1)
xg_gemm(const float* __restrict__ x,
        const float* __restrict__ Wih,
        const float* __restrict__ bih,
        const float* __restrict__ bhh) {
    extern __shared__ float smg[];
    float* xs = smg;                 // [128][64]
    float* ws = smg + 128 * 64;      // [96][68] padded

    const int tid = threadIdx.x;
    const int r0 = blockIdx.x * 128;
    const int cb = blockIdx.y;       // 0..3 -> 96 gate-cols each

    {
        const float4* xg4 = (const float4*)(x + (size_t)r0 * 64);
        float4* xs4 = (float4*)xs;
        #pragma unroll
        for (int i = tid; i < 128 * 16; i += 256) xs4[i] = xg4[i];
    }
    {
        const float4* wg4 = (const float4*)(Wih + (size_t)cb * 96 * 64);
        #pragma unroll
        for (int i = tid; i < 96 * 16; i += 256) {
            int g = i >> 4, k4 = i & 15;
            *(float4*)(ws + g * 68 + k4 * 4) = wg4[i];
        }
    }
    __syncthreads();

    const int ry = tid >> 4;
    const int cx = tid & 15;

    unsigned long long acc[8][6];
    #pragma unroll
    for (int i = 0; i < 8; i++)
        #pragma unroll
        for (int jj = 0; jj < 6; jj++) acc[i][jj] = 0ULL;

    #pragma unroll
    for (int k4 = 0; k4 < 16; k4++) {
        ulonglong2 wv[6];
        #pragma unroll
        for (int jj = 0; jj < 6; jj++)
            wv[jj] = *(const ulonglong2*)(ws + (cx + 16 * jj) * 68 + k4 * 4);
        #pragma unroll
        for (int i = 0; i < 8; i++) {
            ulonglong2 xv = *(const ulonglong2*)(xs + (ry * 8 + i) * 64 + k4 * 4);
            #pragma unroll
            for (int jj = 0; jj < 6; jj++) {
                ffma2(acc[i][jj], xv.x, wv[jj].x);
                ffma2(acc[i][jj], xv.y, wv[jj].y);
            }
        }
    }

    #pragma unroll
    for (int jj = 0; jj < 6; jj++) {
        const int g = cb * 96 + cx + 16 * jj;
        const float bias = bih[g] + (g < 256 ? bhh[g] : 0.0f);
        #pragma unroll
        for (int i = 0; i < 8; i++) {
            const int r = r0 + ry * 8 + i;
            g_xg[(size_t)r * G3 + g] = hsum2(acc[i][jj]) + bias;
        }
    }
}

// ---------------------------------------------------------------------------
// Kernel 2: GRU recurrence + final FC.
// 128 blocks x 4 batches, 256 threads. Thread: j = tid>>1 (hidden unit),
// half = tid&1 (k-half). ALL 3 gate W row-halves in REGISTERS (96 regs).
// h double-buffered in smem, half1 offset padded by 4 floats. One barrier
// per step; cross-half reduction via shfl_xor(.,1) (partner = adjacent lane).
// Each thread computes gates for its 2 batches {2*half, 2*half+1}.
// ---------------------------------------------------------------------------
#define HROW 136   // padded per-batch h row: half0 at [0,64), half1 at [68,132)
__device__ __forceinline__ int hpos(int k) { return k + ((k >> 6) << 2); }

__global__ void __launch_bounds__(256, 1)
gru_kernel(const float* __restrict__ Whh,
           const float* __restrict__ bhh,
           const float* __restrict__ Wfc,
           const float* __restrict__ bfc,
           float* __restrict__ out) {
    __shared__ __align__(16) float hs[2 * 4 * HROW];

    const int tid = threadIdx.x;
    const int j = tid >> 1;      // 0..127
    const int half = tid & 1;    // k-half
    const int b0 = blockIdx.x * 4;

    // Zero read-buffer 0 (t=0 reads it)
    for (int i = tid; i < 4 * HROW; i += 256) hs[i] = 0.0f;

    // One-time: W_hh row-halves (r,z,n for unit j, this k-half) -> registers
    ulonglong2 wrr[16], wzr[16], wnr[16];
    {
        const ulonglong2* wr_g = (const ulonglong2*)(Whh + (size_t)j * 128 + half * 64);
        const ulonglong2* wz_g = (const ulonglong2*)(Whh + (size_t)(j + 128) * 128 + half * 64);
        const ulonglong2* wn_g = (const ulonglong2*)(Whh + (size_t)(j + 256) * 128 + half * 64);
        #pragma unroll
        for (int kk = 0; kk < 16; kk++) {
            wrr[kk] = wr_g[kk];
            wzr[kk] = wz_g[kk];
            wnr[kk] = wn_g[kk];
        }
    }
    const float bn = bhh[256 + j];        // n-gate hidden bias (inside r*(...))
    float hold[2] = {0.f, 0.f};           // own h[j] for batches 2h, 2h+1

    const size_t xgA = ((size_t)(b0 + 2 * half) * Tn) * G3 + j;
    const size_t xgB = ((size_t)(b0 + 2 * half + 1) * Tn) * G3 + j;

    __syncthreads();

    for (int t = 0; t < Tn; t++) {
        const float* hrd = hs + (t & 1) * (4 * HROW);
        float* hwr = hs + ((t & 1) ^ 1) * (4 * HROW);

        // Prefetch this thread's 2 batches' input projections (DRAM, hidden
        // under the ~1536-cyc dot below)
        const float* xpA = g_xg + xgA + (size_t)t * G3;
        const float* xpB = g_xg + xgB + (size_t)t * G3;
        float xr0 = xpA[0], xz0 = xpA[128], xn0 = xpA[256];
        float xr1 = xpB[0], xz1 = xpB[128], xn1 = xpB[256];

        unsigned long long acc[3][4];
        #pragma unroll
        for (int g = 0; g < 3; g++)
            #pragma unroll
            for (int b = 0; b < 4; b++) acc[g][b] = 0ULL;

        const float* hbase = hrd + half * 68;
        #pragma unroll
        for (int kk = 0; kk < 16; kk++) {
            const ulonglong2 wr = wrr[kk], wz = wzr[kk], wn = wnr[kk];
            #pragma unroll
            for (int b = 0; b < 4; b++) {
                ulonglong2 hv = *(const ulonglong2*)(hbase + b * HROW + kk * 4);
                ffma2(acc[0][b], wr.x, hv.x); ffma2(acc[0][b], wr.y, hv.y);
                ffma2(acc[1][b], wz.x, hv.x); ffma2(acc[1][b], wz.y, hv.y);
                ffma2(acc[2][b], wn.x, hv.x); ffma2(acc[2][b], wn.y, hv.y);
            }
        }

        // Horizontal sums (12 per thread)
        float s[3][4];
        #pragma unroll
        for (int g = 0; g < 3; g++)
            #pragma unroll
            for (int b = 0; b < 4; b++) s[g][b] = hsum2(acc[g][b]);

        // Cross-half reduce-scatter with partner lane (tid^1). I keep batches
        // {2*half, 2*half+1}; I send my partials of the OTHER pair. Scalar
        // SELs only (no dynamic array indexing -> no local memory).
        float tot[3][2];
        #pragma unroll
        for (int g = 0; g < 3; g++) {
            #pragma unroll
            for (int i = 0; i < 2; i++) {
                float keepv = half ? s[g][2 + i] : s[g][i];
                float sendv = half ? s[g][i] : s[g][2 + i];
                tot[g][i] = keepv + __shfl_xor_sync(0xFFFFFFFFu, sendv, 1);
            }
        }

        // Gates for (j, b = 2*half + i)
        {
            float r0g = sigf(xr0 + tot[0][0]);
            float z0g = sigf(xz0 + tot[1][0]);
            float n0g = tanh_fast(fmaf(r0g, tot[2][0] + bn, xn0));
            float h0n = fmaf(z0g, hold[0] - n0g, n0g);
            hold[0] = h0n;
            hwr[(2 * half + 0) * HROW + hpos(j)] = h0n;

            float r1g = sigf(xr1 + tot[0][1]);
            float z1g = sigf(xz1 + tot[1][1]);
            float n1g = tanh_fast(fmaf(r1g, tot[2][1] + bn, xn1));
            float h1n = fmaf(z1g, hold[1] - n1g, n1g);
            hold[1] = h1n;
            hwr[(2 * half + 1) * HROW + hpos(j)] = h1n;
        }

        __syncthreads();
    }

    // Final h is in buffer 0 (t=1023 writes buf (1023+1)&1 = 0).
    // FC: out[b][o] = h_T[b] . W_fc[o] + b_fc[o]
    if (tid < 4 * 51) {
        const int b = tid / 51, o = tid % 51;
        float a = bfc[o];
        const float* wf = Wfc + o * 128;
        const float* hp = hs + b * HROW;
        #pragma unroll 8
        for (int k = 0; k < 128; k++) a = fmaf(hp[hpos(k)], wf[k], a);
        out[(b0 + b) * 51 + o] = a;
    }
}

// ---------------------------------------------------------------------------
// Launch
// ---------------------------------------------------------------------------
extern "C" void kernel_launch(void* const* d_in, const int* in_sizes, int n_in,
                              void* d_out, int out_size) {
    const float* x    = (const float*)d_in[0];  // [512,1,1024,64]
    const float* Wih  = (const float*)d_in[1];  // [384,64]
    const float* Whh  = (const float*)d_in[2];  // [384,128]
    const float* bih  = (const float*)d_in[3];  // [384]
    const float* bhh  = (const float*)d_in[4];  // [384]
    const float* Wfc  = (const float*)d_in[5];  // [51,128]
    const float* bfc  = (const float*)d_in[6];  // [51]
    float* out = (float*)d_out;                 // [512,51]

    static int attr_done = 0;
    if (!attr_done) {
        cudaFuncSetAttribute(xg_gemm,
                             cudaFuncAttributeMaxDynamicSharedMemorySize,
                             XG_SMEM_BYTES);
        attr_done = 1;
    }

    xg_gemm<<<dim3((Bn * Tn) / 128, 4, 1), 256, XG_SMEM_BYTES>>>(x, Wih, bih, bhh);
    gru_kernel<<<128, 256>>>(Whh, bhh, Wfc, bfc, out);
}